// round 2
// baseline (speedup 1.0000x reference)
#include <cuda_runtime.h>
#include <cuda_bf16.h>
#include <cstdint>

// ============================================================
// Problem sizes (fixed by the dataset)
// ============================================================
static constexpr int MM = 16384;   // B*S tokens
static constexpr int KK = 2048;    // D_IN
static constexpr int NN = 2048;    // D_OUT

// GEMM tiling (int8 mma.sync path — tcgen05 is not available: harness PTX
// targets plain sm_103, which rejects all 'a'-suffix features)
static constexpr int GM_TILE  = 128;
static constexpr int GN_TILE  = 128;
static constexpr int GK_STAGE = 128;                 // int8 elems per stage (128B rows)
static constexpr int GKITERS  = KK / GK_STAGE;       // 16
static constexpr int GSTAGES  = 3;
static constexpr int AST_BYTES = GM_TILE * 128;      // 16 KB
static constexpr int STG_BYTES = 2 * AST_BYTES;      // 32 KB (A + B)
static constexpr int GEMM_SMEM = GSTAGES * STG_BYTES; // 98304

// ============================================================
// Device scratch (static — no allocation allowed)
// ============================================================
__device__ __align__(1024) int8_t g_act8[(size_t)MM * KK];  // 32 MB
__device__ __align__(1024) int8_t g_wq8[(size_t)NN * KK];   //  4 MB
__device__ float g_rowscale[MM];
__device__ float g_wpart[NN];
__device__ float g_wscale;   // = max(mean|W|, eps) = 1/s_w
__device__ float g_sw;       // = s_w

// ============================================================
// PTX helpers
// ============================================================
__device__ __forceinline__ uint32_t smem_u32(const void* p) {
    uint32_t a;
    asm("{ .reg .u64 t; cvta.to.shared.u64 t, %1; cvt.u32.u64 %0, t; }" : "=r"(a) : "l"(p));
    return a;
}

#define CP_ASYNC16(smem_addr, gmem_ptr) \
    asm volatile("cp.async.cg.shared.global [%0], [%1], 16;" \
        :: "r"(smem_addr), "l"(gmem_ptr) : "memory")
#define CP_COMMIT() asm volatile("cp.async.commit_group;" ::: "memory")
#define CP_WAIT(n)  asm volatile("cp.async.wait_group %0;" :: "n"(n) : "memory")

// int8 x int8 -> s32 tensor-core MMA (sm_80+ base ISA, works on sm_103)
#define MMA_S8(c, a, b) \
    asm volatile( \
        "mma.sync.aligned.m16n8k32.row.col.s32.s8.s8.s32 " \
        "{%0,%1,%2,%3}, {%4,%5,%6,%7}, {%8,%9}, {%0,%1,%2,%3};" \
        : "+r"((c)[0]), "+r"((c)[1]), "+r"((c)[2]), "+r"((c)[3]) \
        : "r"((a)[0]), "r"((a)[1]), "r"((a)[2]), "r"((a)[3]), \
          "r"((b)[0]), "r"((b)[1]))

__device__ __forceinline__ uint32_t pack4_s8(float q0, float q1, float q2, float q3) {
    int i0 = (int)q0, i1 = (int)q1, i2 = (int)q2, i3 = (int)q3;
    return (uint32_t)(i0 & 255) | ((uint32_t)(i1 & 255) << 8) |
           ((uint32_t)(i2 & 255) << 16) | ((uint32_t)(i3 & 255) << 24);
}

// ============================================================
// Kernel 1: per-row |W| sums (deterministic)
// ============================================================
__global__ void __launch_bounds__(256) wabs_kernel(const float* __restrict__ w) {
    __shared__ float red[256];
    int row = blockIdx.x, t = threadIdx.x;
    const float4* wr = reinterpret_cast<const float4*>(w) + (size_t)row * (KK / 4);
    float4 a = wr[t], b = wr[256 + t];
    float s = fabsf(a.x) + fabsf(a.y) + fabsf(a.z) + fabsf(a.w)
            + fabsf(b.x) + fabsf(b.y) + fabsf(b.z) + fabsf(b.w);
    red[t] = s; __syncthreads();
    for (int o = 128; o > 0; o >>= 1) { if (t < o) red[t] += red[t + o]; __syncthreads(); }
    if (t == 0) g_wpart[row] = red[0];
}

// Kernel 2: finalize s_w
__global__ void __launch_bounds__(256) wfinal_kernel() {
    __shared__ float red[256];
    int t = threadIdx.x;
    float s = 0.f;
    #pragma unroll
    for (int i = 0; i < NN / 256; i++) s += g_wpart[t + i * 256];
    red[t] = s; __syncthreads();
    for (int o = 128; o > 0; o >>= 1) { if (t < o) red[t] += red[t + o]; __syncthreads(); }
    if (t == 0) {
        float mean = red[0] * (1.0f / ((float)NN * (float)KK));
        float ws = fmaxf(mean, 1e-8f);
        g_wscale = ws;         // 1/s_w
        g_sw = 1.0f / ws;      // s_w
    }
}

// Kernel 3: ternarize weight -> int8 in {-1,0,1}
__global__ void __launch_bounds__(256) ternarize_kernel(const float* __restrict__ w) {
    int i = blockIdx.x * 256 + threadIdx.x;   // float4 index, total NN*KK/4
    float sw = g_sw;
    float4 v = reinterpret_cast<const float4*>(w)[i];
    float t0 = fminf(fmaxf(rintf(sw * v.x), -1.f), 1.f);
    float t1 = fminf(fmaxf(rintf(sw * v.y), -1.f), 1.f);
    float t2 = fminf(fmaxf(rintf(sw * v.z), -1.f), 1.f);
    float t3 = fminf(fmaxf(rintf(sw * v.w), -1.f), 1.f);
    reinterpret_cast<uint32_t*>(g_wq8)[i] = pack4_s8(t0, t1, t2, t3);
}

// ============================================================
// Kernel 4: LayerNorm + per-token int8 fake-quant -> int8 q + row scale
// One CTA (256 threads) per token row of 2048 floats.
// ============================================================
__global__ void __launch_bounds__(256) ln_quant_kernel(const float* __restrict__ x) {
    __shared__ float red[256];
    __shared__ float redm[256];
    int row = blockIdx.x, t = threadIdx.x;
    const float4* xr = reinterpret_cast<const float4*>(x) + (size_t)row * (KK / 4);
    float4 a = xr[t], b = xr[256 + t];
    float s = a.x + a.y + a.z + a.w + b.x + b.y + b.z + b.w;
    red[t] = s; __syncthreads();
    for (int o = 128; o > 0; o >>= 1) { if (t < o) red[t] += red[t + o]; __syncthreads(); }
    float mu = red[0] * (1.0f / (float)KK);
    __syncthreads();

    float d0 = a.x - mu, d1 = a.y - mu, d2 = a.z - mu, d3 = a.w - mu;
    float d4 = b.x - mu, d5 = b.y - mu, d6 = b.z - mu, d7 = b.w - mu;
    float sq = d0*d0 + d1*d1 + d2*d2 + d3*d3 + d4*d4 + d5*d5 + d6*d6 + d7*d7;
    float mx = fmaxf(fmaxf(fmaxf(fabsf(d0), fabsf(d1)), fmaxf(fabsf(d2), fabsf(d3))),
                     fmaxf(fmaxf(fabsf(d4), fabsf(d5)), fmaxf(fabsf(d6), fabsf(d7))));
    red[t] = sq; redm[t] = mx; __syncthreads();
    for (int o = 128; o > 0; o >>= 1) {
        if (t < o) { red[t] += red[t + o]; redm[t] = fmaxf(redm[t], redm[t + o]); }
        __syncthreads();
    }
    float var = red[0] * (1.0f / (float)KK);
    float r = 1.0f / sqrtf(var + 1e-8f);
    float amax = fmaxf(r * redm[0], 1e-8f);
    float sact = 127.0f / amax;
    if (t == 0) g_rowscale[row] = (amax * (1.0f / 127.0f)) * g_wscale;

    uint32_t* arow = reinterpret_cast<uint32_t*>(g_act8 + (size_t)row * KK);
    {
        float q0 = fminf(fmaxf(rintf(sact * (r * d0)), -128.f), 127.f);
        float q1 = fminf(fmaxf(rintf(sact * (r * d1)), -128.f), 127.f);
        float q2 = fminf(fmaxf(rintf(sact * (r * d2)), -128.f), 127.f);
        float q3 = fminf(fmaxf(rintf(sact * (r * d3)), -128.f), 127.f);
        arow[t] = pack4_s8(q0, q1, q2, q3);
    }
    {
        float q0 = fminf(fmaxf(rintf(sact * (r * d4)), -128.f), 127.f);
        float q1 = fminf(fmaxf(rintf(sact * (r * d5)), -128.f), 127.f);
        float q2 = fminf(fmaxf(rintf(sact * (r * d6)), -128.f), 127.f);
        float q3 = fminf(fmaxf(rintf(sact * (r * d7)), -128.f), 127.f);
        arow[256 + t] = pack4_s8(q0, q1, q2, q3);
    }
}

// ============================================================
// Kernel 5: int8 tensor-core GEMM  out[M,N] = act[M,K] @ wq[N,K]^T
// CTA tile 128x128, 3-stage cp.async pipeline, mma.m16n8k32.s8
// 8 warps = 2(m) x 4(n), warp tile 64x32
// ============================================================
__global__ void __launch_bounds__(256, 2)
gemm_kernel(const float* __restrict__ bias, float* __restrict__ out) {
    extern __shared__ __align__(128) char smem[];
    const uint32_t sbase = smem_u32(smem);
    const int tid = threadIdx.x, lane = tid & 31, wid = tid >> 5;
    const int wm = wid >> 2, wn = wid & 3;        // warp grid 2x4
    const int m0 = (int)(blockIdx.x >> 4) * GM_TILE;
    const int n0 = (int)(blockIdx.x & 15) * GN_TILE;

    const int8_t* Ag = g_act8 + (size_t)m0 * KK;
    const int8_t* Bg = g_wq8 + (size_t)n0 * KK;

    int acc[4][4][4];
    #pragma unroll
    for (int i = 0; i < 4; i++)
        #pragma unroll
        for (int j = 0; j < 4; j++)
            #pragma unroll
            for (int k = 0; k < 4; k++) acc[i][j][k] = 0;

    // -------- stage loader: 8 x cp.async(16B) per thread --------
    auto load_stage = [&](int it, int s) {
        uint32_t As = sbase + s * STG_BYTES;
        uint32_t Bs = As + AST_BYTES;
        #pragma unroll
        for (int i = 0; i < 4; i++) {
            int cc = tid + i * 256;               // 1024 chunks of 16B
            int row = cc >> 3, u = cc & 7;
            uint32_t so = row * 128 + ((u ^ (row & 7)) << 4);
            CP_ASYNC16(As + so, Ag + (size_t)row * KK + it * GK_STAGE + u * 16);
            CP_ASYNC16(Bs + so, Bg + (size_t)row * KK + it * GK_STAGE + u * 16);
        }
    };

    load_stage(0, 0); CP_COMMIT();
    load_stage(1, 1); CP_COMMIT();

    for (int it = 0; it < GKITERS; ++it) {
        int s = it % GSTAGES;
        CP_WAIT(1);
        __syncthreads();
        if (it + 2 < GKITERS) load_stage(it + 2, (it + 2) % GSTAGES);
        CP_COMMIT();

        uint32_t As = sbase + s * STG_BYTES;
        uint32_t Bs = As + AST_BYTES;
        #pragma unroll
        for (int kk = 0; kk < 4; ++kk) {          // 4 x K=32 per stage
            uint32_t a[4][4];
            #pragma unroll
            for (int mi = 0; mi < 4; mi++) {
                int row0 = wm * 64 + mi * 16 + (lane >> 2);
                #pragma unroll
                for (int r = 0; r < 4; r++) {
                    int row = row0 + ((r & 1) << 3);       // a0:r, a1:r+8, a2:r(k+16), a3:r+8(k+16)
                    int u = kk * 2 + (r >> 1);
                    uint32_t addr = As + row * 128 + ((u ^ (row & 7)) << 4) + ((lane & 3) << 2);
                    asm volatile("ld.shared.b32 %0, [%1];" : "=r"(a[mi][r]) : "r"(addr));
                }
            }
            uint32_t b[4][2];
            #pragma unroll
            for (int ni = 0; ni < 4; ni++) {
                int rowb = wn * 32 + ni * 8 + (lane >> 2);
                #pragma unroll
                for (int r = 0; r < 2; r++) {
                    int u = kk * 2 + r;
                    uint32_t addr = Bs + rowb * 128 + ((u ^ (rowb & 7)) << 4) + ((lane & 3) << 2);
                    asm volatile("ld.shared.b32 %0, [%1];" : "=r"(b[ni][r]) : "r"(addr));
                }
            }
            #pragma unroll
            for (int mi = 0; mi < 4; mi++)
                #pragma unroll
                for (int ni = 0; ni < 4; ni++)
                    MMA_S8(acc[mi][ni], a[mi], b[ni]);
        }
        __syncthreads();
    }

    // -------- epilogue: scale + bias, float2 stores --------
    #pragma unroll
    for (int mi = 0; mi < 4; mi++) {
        int row0 = m0 + wm * 64 + mi * 16 + (lane >> 2);
        float rs0 = g_rowscale[row0];
        float rs1 = g_rowscale[row0 + 8];
        #pragma unroll
        for (int ni = 0; ni < 4; ni++) {
            int col = n0 + wn * 32 + ni * 8 + ((lane & 3) << 1);
            float b0 = bias[col], b1 = bias[col + 1];
            const int* cc = acc[mi][ni];
            float2 v0 = make_float2(__int2float_rn(cc[0]) * rs0 + b0,
                                    __int2float_rn(cc[1]) * rs0 + b1);
            float2 v1 = make_float2(__int2float_rn(cc[2]) * rs1 + b0,
                                    __int2float_rn(cc[3]) * rs1 + b1);
            *reinterpret_cast<float2*>(out + (size_t)row0 * NN + col) = v0;
            *reinterpret_cast<float2*>(out + (size_t)(row0 + 8) * NN + col) = v1;
        }
    }
}

// ============================================================
// Host side
// ============================================================
extern "C" void kernel_launch(void* const* d_in, const int* in_sizes, int n_in,
                              void* d_out, int out_size) {
    const float* x    = (const float*)d_in[0];
    const float* w    = (const float*)d_in[1];
    const float* bias = (const float*)d_in[2];
    float* out = (float*)d_out;

    wabs_kernel<<<NN, 256>>>(w);
    wfinal_kernel<<<1, 256>>>();
    ternarize_kernel<<<(NN * KK / 4) / 256, 256>>>(w);
    ln_quant_kernel<<<MM, 256>>>(x);

    static bool attr_set = false;
    if (!attr_set) {
        cudaFuncSetAttribute(gemm_kernel, cudaFuncAttributeMaxDynamicSharedMemorySize, GEMM_SMEM);
        attr_set = true;
    }
    dim3 grid((MM / GM_TILE) * (NN / GN_TILE));   // 128 * 16 = 2048 CTAs
    gemm_kernel<<<grid, 256, GEMM_SMEM>>>(bias, out);
}